// round 16
// baseline (speedup 1.0000x reference)
#include <cuda_runtime.h>
#include <cstdint>

// ---------------------------------------------------------------------------
// patches [16384][9] f32, db [16384][9] f32.
// mask[i] = all_j ( dot(p_i,d_j) / (||p_i|| ||d_j||) < 0.9 )
// out = [ db (147456 f32) ; mask[i] ? p_i : 0 (147456 f32) ]
//
// 4 early-exit rounds over j with worklist compaction; db tile in smem;
// threshold folded into the FMA chain, miss tracked via sign-bit AND.
// Single-wave grids (512 blocks @ 4 CTAs/SM).
// ---------------------------------------------------------------------------

#define N_PATCH  16384
#define N_DB     16384
#define ROW      9
#define DUMMY    N_PATCH
#define HALF_OUT (N_DB * ROW)           // 147456
#define TOTAL_OUT (2 * HALF_OUT)        // 294912

typedef unsigned long long ull;

// db rows pre-normalized, duplicated for f32x2: [d0,d0,...,d8,d8,pad,pad]
__device__ ulonglong2 g_dn2[N_DB * 5];
// per-patch packed: 3 x float4 = [c0..c3][c4..c7][c8, -thr, 0, 0]
__device__ float4 g_pp[(N_PATCH + 1) * 3];
__device__ int g_hit[N_PATCH];
__device__ int g_listA[N_PATCH];
__device__ int g_listB[N_PATCH];
__device__ int g_cnt[3];

// ------------------------- f32x2 helpers -----------------------------------
__device__ __forceinline__ ull pack2(float a, float b) {
    ull r; asm("mov.b64 %0, {%1, %2};" : "=l"(r) : "f"(a), "f"(b)); return r;
}
__device__ __forceinline__ ull fma2(ull a, ull b, ull c) {
    ull r; asm("fma.rn.f32x2 %0, %1, %2, %3;" : "=l"(r) : "l"(a), "l"(b), "l"(c));
    return r;
}

// ------------------------- prep kernel -------------------------------------
__global__ void prep_kernel(const float* __restrict__ patches,
                            const float* __restrict__ db) {
    int idx = blockIdx.x * blockDim.x + threadIdx.x;
    if (idx < N_DB) {
        const float* s = db + idx * ROW;
        float v[ROW];
        float acc = 0.0f;
#pragma unroll
        for (int k = 0; k < ROW; k++) { v[k] = s[k]; acc = fmaf(v[k], v[k], acc); }
        float inv = (float)(1.0 / sqrt((double)acc));
        float* o = (float*)(g_dn2 + (size_t)idx * 5);
#pragma unroll
        for (int k = 0; k < ROW; k++) {
            float w = v[k] * inv;
            o[2 * k] = w; o[2 * k + 1] = w;
        }
        o[18] = 0.0f; o[19] = 0.0f;
        g_hit[idx] = 0;
        if (idx < 3) g_cnt[idx] = 0;
        if (idx == 0) {   // dummy patch: zero coords, -thr = -1e30 (never hits)
            float4 z = make_float4(0.f, 0.f, 0.f, 0.f);
            g_pp[DUMMY * 3 + 0] = z;
            g_pp[DUMMY * 3 + 1] = z;
            g_pp[DUMMY * 3 + 2] = make_float4(0.f, -1.0e30f, 0.f, 0.f);
        }
    } else if (idx < N_DB + N_PATCH) {
        int i = idx - N_DB;
        const float* s = patches + (size_t)i * ROW;
        float v[ROW];
        float acc = 0.0f;
#pragma unroll
        for (int k = 0; k < ROW; k++) { v[k] = s[k]; acc = fmaf(v[k], v[k], acc); }
        float negthr = -(float)(0.9 * sqrt((double)acc));
        g_pp[i * 3 + 0] = make_float4(v[0], v[1], v[2], v[3]);
        g_pp[i * 3 + 1] = make_float4(v[4], v[5], v[6], v[7]);
        g_pp[i * 3 + 2] = make_float4(v[8], negthr, 0.f, 0.f);
    }
}

// ------------------------- similarity round --------------------------------
#define B_THREADS 128
#define NPAIR     4                      // pairs per thread = 8 patches
#define PPB       (B_THREADS * NPAIR * 2)   // 1024 patches per x-tile
#define JCHUNK    32
#define UNROLL    2

__global__ __launch_bounds__(B_THREADS, 4)
void sim_kernel(int jbase, const int* __restrict__ list,
                const int* __restrict__ cntp) {
    __shared__ ulonglong2 s_db[JCHUNK * 5];          // 2.5 KB db tile

    const int tid = threadIdx.x;
    const int cnt = list ? *cntp : N_PATCH;

    // Cooperative tile load: 160 x 16B, depends only on blockIdx.y
    {
        const ulonglong2* src = g_dn2 + (size_t)(jbase + blockIdx.y * JCHUNK) * 5;
#pragma unroll
        for (int t = 0; t < 2; t++) {
            int k = tid + t * B_THREADS;
            if (k < JCHUNK * 5) s_db[k] = src[k];
        }
    }
    __syncthreads();

    for (int base = blockIdx.x * PPB; base < cnt; base += gridDim.x * PPB) {
        // Resolve this thread's 8 patch indices (dummy beyond cnt)
        int ia[NPAIR], ib[NPAIR];
#pragma unroll
        for (int pr = 0; pr < NPAIR; pr++) {
            int s0 = base + tid * (2 * NPAIR) + 2 * pr;
            int s1 = s0 + 1;
            ia[pr] = (s0 < cnt) ? (list ? list[s0] : s0) : DUMMY;
            ib[pr] = (s1 < cnt) ? (list ? list[s1] : s1) : DUMMY;
        }

        // Pack pairs: 9 f32x2 coords + packed negated thresholds
        ull pk[NPAIR][ROW];
        ull negt[NPAIR];
#pragma unroll
        for (int pr = 0; pr < NPAIR; pr++) {
            float4 a0 = g_pp[ia[pr] * 3 + 0], a1 = g_pp[ia[pr] * 3 + 1],
                   a2 = g_pp[ia[pr] * 3 + 2];
            float4 b0 = g_pp[ib[pr] * 3 + 0], b1 = g_pp[ib[pr] * 3 + 1],
                   b2 = g_pp[ib[pr] * 3 + 2];
            pk[pr][0] = pack2(a0.x, b0.x); pk[pr][1] = pack2(a0.y, b0.y);
            pk[pr][2] = pack2(a0.z, b0.z); pk[pr][3] = pack2(a0.w, b0.w);
            pk[pr][4] = pack2(a1.x, b1.x); pk[pr][5] = pack2(a1.y, b1.y);
            pk[pr][6] = pack2(a1.z, b1.z); pk[pr][7] = pack2(a1.w, b1.w);
            pk[pr][8] = pack2(a2.x, b2.x);
            negt[pr]  = pack2(a2.y, b2.y);   // (-thrA, -thrB)
        }

        // all-miss sign accumulators: sign bit stays 1 iff every j missed
        unsigned mlo[NPAIR], mhi[NPAIR];
#pragma unroll
        for (int pr = 0; pr < NPAIR; pr++) { mlo[pr] = 0xFFFFFFFFu; mhi[pr] = 0xFFFFFFFFu; }

#pragma unroll 1
        for (int j = 0; j < JCHUNK; j += UNROLL) {
#pragma unroll
            for (int u = 0; u < UNROLL; u++) {
                const ulonglong2* q = s_db + (j + u) * 5;
                const ulonglong2 q0 = q[0];
                const ulonglong2 q1 = q[1];
                const ulonglong2 q2 = q[2];
                const ulonglong2 q3 = q[3];
                const ulonglong2 q4 = q[4];
#pragma unroll
                for (int pr = 0; pr < NPAIR; pr++) {
                    // acc = dot - thr (both halves); hit iff acc >= +0
                    ull acc = fma2(pk[pr][0], q0.x, negt[pr]);
                    acc = fma2(pk[pr][1], q0.y, acc);
                    acc = fma2(pk[pr][2], q1.x, acc);
                    acc = fma2(pk[pr][3], q1.y, acc);
                    acc = fma2(pk[pr][4], q2.x, acc);
                    acc = fma2(pk[pr][5], q2.y, acc);
                    acc = fma2(pk[pr][6], q3.x, acc);
                    acc = fma2(pk[pr][7], q3.y, acc);
                    acc = fma2(pk[pr][8], q4.x, acc);
                    mlo[pr] &= (unsigned)acc;          // LOP3 on low reg
                    mhi[pr] &= (unsigned)(acc >> 32);  // LOP3 on high reg
                }
            }
        }

#pragma unroll
        for (int pr = 0; pr < NPAIR; pr++) {
            if (!(mlo[pr] & 0x80000000u) && ia[pr] < N_PATCH)
                ((volatile int*)g_hit)[ia[pr]] = 1;   // benign race: same value
            if (!(mhi[pr] & 0x80000000u) && ib[pr] < N_PATCH)
                ((volatile int*)g_hit)[ib[pr]] = 1;
        }
    }
}

// ------------------------- compaction --------------------------------------
__global__ void compact_kernel(int* __restrict__ outlist, int* __restrict__ cntslot) {
    int i = blockIdx.x * blockDim.x + threadIdx.x;
    bool surv = (i < N_PATCH) && (g_hit[i] == 0);
    unsigned ballot = __ballot_sync(0xFFFFFFFFu, surv);
    int lane = threadIdx.x & 31;
    int rank = __popc(ballot & ((1u << lane) - 1));
    int total = __popc(ballot);
    int basepos = 0;
    if (lane == 0 && total) basepos = atomicAdd(cntslot, total);
    basepos = __shfl_sync(0xFFFFFFFFu, basepos, 0);
    if (surv) outlist[basepos + rank] = i;
}

// ------------------------- output kernel -----------------------------------
__global__ void out_kernel(const float4* __restrict__ patches4,
                           const float4* __restrict__ db4,
                           float4* __restrict__ out4) {
    int idx = blockIdx.x * blockDim.x + threadIdx.x;
    if (idx < HALF_OUT / 4) {
        out4[idx] = db4[idx];
    } else if (idx < TOTAL_OUT / 4) {
        int t4 = idx - HALF_OUT / 4;
        float4 v = patches4[t4];
        float w[4] = {v.x, v.y, v.z, v.w};
        int t = t4 * 4;
#pragma unroll
        for (int k = 0; k < 4; k++)
            if (g_hit[(t + k) / ROW]) w[k] = 0.0f;
        out4[idx] = make_float4(w[0], w[1], w[2], w[3]);
    }
}

// ------------------------- launch ------------------------------------------
extern "C" void kernel_launch(void* const* d_in, const int* in_sizes, int n_in,
                              void* d_out, int out_size) {
    const float* patches = (const float*)d_in[0];   // [16384][9]
    const float* db      = (const float*)d_in[1];   // [16384][9]

    int *listA, *listB, *cnt;
    cudaGetSymbolAddress((void**)&listA, g_listA);
    cudaGetSymbolAddress((void**)&listB, g_listB);
    cudaGetSymbolAddress((void**)&cnt,   g_cnt);

    prep_kernel<<<(N_DB + N_PATCH + 255) / 256, 256>>>(patches, db);

    // All rounds: 512 blocks = one full wave at 4 CTAs/SM (592 capacity).
    // Round 0: j [0, 2048), all patches        -> 8 x 64 (2 x-tiles each)
    sim_kernel<<<dim3(8, 64), B_THREADS>>>(0, nullptr, nullptr);
    compact_kernel<<<N_PATCH / 256, 256>>>(listA, cnt + 0);
    // Round 1: j [2048, 4096), survivors       -> 8 x 64
    sim_kernel<<<dim3(8, 64), B_THREADS>>>(2048, listA, cnt + 0);
    compact_kernel<<<N_PATCH / 256, 256>>>(listB, cnt + 1);
    // Round 2: j [4096, 8192), survivors       -> 4 x 128
    sim_kernel<<<dim3(4, 128), B_THREADS>>>(4096, listB, cnt + 1);
    compact_kernel<<<N_PATCH / 256, 256>>>(listA, cnt + 2);
    // Round 3: j [8192, 16384), survivors      -> 2 x 256
    sim_kernel<<<dim3(2, 256), B_THREADS>>>(8192, listA, cnt + 2);

    out_kernel<<<(TOTAL_OUT / 4 + 255) / 256, 256>>>(
        (const float4*)patches, (const float4*)db, (float4*)d_out);
}

// round 17
// speedup vs baseline: 1.5498x; 1.5498x over previous
#include <cuda_runtime.h>
#include <cstdint>

// ---------------------------------------------------------------------------
// patches [16384][9] f32, db [16384][9] f32.
// mask[i] = all_j ( dot(p_i,d_j) / (||p_i|| ||d_j||) < 0.9 )
// out = [ db (147456 f32) ; mask[i] ? p_i : 0 (147456 f32) ]
//
// 4 early-exit rounds over j with compaction + re-pairing (gather) between
// rounds. Patch pairs stored pre-packed for f32x2; db tile in smem;
// threshold folded into FMA chain; miss via sign-bit AND (merged LOP3).
// ---------------------------------------------------------------------------

#define N_PATCH  16384
#define N_DB     16384
#define ROW      9
#define DUMMY    N_PATCH
#define MAXPAIR  (N_PATCH / 2)          // 8192
#define HALF_OUT (N_DB * ROW)           // 147456
#define TOTAL_OUT (2 * HALF_OUT)        // 294912

typedef unsigned long long ull;

// db rows pre-normalized, duplicated for f32x2: [d0,d0,...,d8,d8,pad,pad]
__device__ ulonglong2 g_dn2[N_DB * 5];
// per-patch record (for gather): 3 x float4 = [c0..c3][c4..c7][c8, -thr, 0, 0]
__device__ float4 g_pp[(N_PATCH + 1) * 3];
// paired-packed records: 5 x ulonglong2 per pair:
//   {(a0,b0),(a1,b1)} {(a2,b2),(a3,b3)} {(a4,b4),(a5,b5)} {(a6,b6),(a7,b7)}
//   {(a8,b8),(-thrA,-thrB)}
__device__ ulonglong2 g_pk[MAXPAIR * 5];
__device__ int2 g_idx[MAXPAIR];         // patch indices of each pair
__device__ int g_hit[N_PATCH];
__device__ int g_list[N_PATCH];
__device__ int g_cnt[3];

// ------------------------- f32x2 helpers -----------------------------------
__device__ __forceinline__ ull pack2(float a, float b) {
    ull r; asm("mov.b64 %0, {%1, %2};" : "=l"(r) : "f"(a), "f"(b)); return r;
}
__device__ __forceinline__ ull fma2(ull a, ull b, ull c) {
    ull r; asm("fma.rn.f32x2 %0, %1, %2, %3;" : "=l"(r) : "l"(a), "l"(b), "l"(c));
    return r;
}

// ------------------------- prep kernel -------------------------------------
// idx < N_DB: normalize db row, zero hit/cnt, dummy patch record.
// idx in [N_DB, N_DB+MAXPAIR): build patch pair pr (round-0 pairing 2pr,2pr+1):
//   per-patch record g_pp, paired record g_pk, indices g_idx.
__global__ void prep_kernel(const float* __restrict__ patches,
                            const float* __restrict__ db) {
    int idx = blockIdx.x * blockDim.x + threadIdx.x;
    if (idx < N_DB) {
        const float* s = db + idx * ROW;
        float v[ROW];
        float acc = 0.0f;
#pragma unroll
        for (int k = 0; k < ROW; k++) { v[k] = s[k]; acc = fmaf(v[k], v[k], acc); }
        float inv = (float)(1.0 / sqrt((double)acc));
        float* o = (float*)(g_dn2 + (size_t)idx * 5);
#pragma unroll
        for (int k = 0; k < ROW; k++) {
            float w = v[k] * inv;
            o[2 * k] = w; o[2 * k + 1] = w;
        }
        o[18] = 0.0f; o[19] = 0.0f;
        g_hit[idx] = 0;
        if (idx < 3) g_cnt[idx] = 0;
        if (idx == 0) {   // dummy patch: zero coords, -thr = -1e30 (never hits)
            float4 z = make_float4(0.f, 0.f, 0.f, 0.f);
            g_pp[DUMMY * 3 + 0] = z;
            g_pp[DUMMY * 3 + 1] = z;
            g_pp[DUMMY * 3 + 2] = make_float4(0.f, -1.0e30f, 0.f, 0.f);
        }
    } else if (idx < N_DB + MAXPAIR) {
        int pr = idx - N_DB;
        const float* s = patches + (size_t)pr * 18;
        float a[ROW], b[ROW];
        float sa = 0.0f, sb = 0.0f;
#pragma unroll
        for (int k = 0; k < ROW; k++) {
            a[k] = s[k];       sa = fmaf(a[k], a[k], sa);
            b[k] = s[ROW + k]; sb = fmaf(b[k], b[k], sb);
        }
        float nta = -(float)(0.9 * sqrt((double)sa));
        float ntb = -(float)(0.9 * sqrt((double)sb));
        int ia = 2 * pr, ib = 2 * pr + 1;
        g_pp[ia * 3 + 0] = make_float4(a[0], a[1], a[2], a[3]);
        g_pp[ia * 3 + 1] = make_float4(a[4], a[5], a[6], a[7]);
        g_pp[ia * 3 + 2] = make_float4(a[8], nta, 0.f, 0.f);
        g_pp[ib * 3 + 0] = make_float4(b[0], b[1], b[2], b[3]);
        g_pp[ib * 3 + 1] = make_float4(b[4], b[5], b[6], b[7]);
        g_pp[ib * 3 + 2] = make_float4(b[8], ntb, 0.f, 0.f);
        ulonglong2* o = g_pk + (size_t)pr * 5;
        o[0] = make_ulonglong2(pack2(a[0], b[0]), pack2(a[1], b[1]));
        o[1] = make_ulonglong2(pack2(a[2], b[2]), pack2(a[3], b[3]));
        o[2] = make_ulonglong2(pack2(a[4], b[4]), pack2(a[5], b[5]));
        o[3] = make_ulonglong2(pack2(a[6], b[6]), pack2(a[7], b[7]));
        o[4] = make_ulonglong2(pack2(a[8], b[8]), pack2(nta, ntb));
        g_idx[pr] = make_int2(ia, ib);
    }
}

// ------------------------- similarity round --------------------------------
#define B_THREADS 128
#define NPAIR     4                      // pairs per thread = 8 patches
#define PRB       (B_THREADS * NPAIR)    // 512 pairs per x-tile
#define JCHUNK    32
#define UNROLL    2

__global__ __launch_bounds__(B_THREADS, 4)
void sim_kernel(int jbase, const int* __restrict__ cntp) {
    __shared__ ulonglong2 s_db[JCHUNK * 5];          // 2.5 KB db tile

    const int tid = threadIdx.x;
    const int np = cntp ? ((*cntp + 1) >> 1) : MAXPAIR;

    // Cooperative tile load: 160 x 16B, depends only on blockIdx.y
    {
        const ulonglong2* src = g_dn2 + (size_t)(jbase + blockIdx.y * JCHUNK) * 5;
#pragma unroll
        for (int t = 0; t < 2; t++) {
            int k = tid + t * B_THREADS;
            if (k < JCHUNK * 5) s_db[k] = src[k];
        }
    }
    __syncthreads();

    for (int base = blockIdx.x * PRB; base < np; base += gridDim.x * PRB) {
        // Load this thread's 4 paired records (5 LDG.128 + 1 LDG.64 each)
        ull pk[NPAIR][ROW];
        ull negt[NPAIR];
        int2 pidx[NPAIR];
#pragma unroll
        for (int pr = 0; pr < NPAIR; pr++) {
            int p = base + tid * NPAIR + pr;
            if (p < np) {
                const ulonglong2* q = g_pk + (size_t)p * 5;
                ulonglong2 v0 = q[0], v1 = q[1], v2 = q[2], v3 = q[3], v4 = q[4];
                pk[pr][0] = v0.x; pk[pr][1] = v0.y;
                pk[pr][2] = v1.x; pk[pr][3] = v1.y;
                pk[pr][4] = v2.x; pk[pr][5] = v2.y;
                pk[pr][6] = v3.x; pk[pr][7] = v3.y;
                pk[pr][8] = v4.x;
                negt[pr]  = v4.y;
                pidx[pr]  = g_idx[p];
            } else {
#pragma unroll
                for (int k = 0; k < ROW; k++) pk[pr][k] = 0ULL;
                negt[pr] = pack2(-1.0e30f, -1.0e30f);
                pidx[pr] = make_int2(DUMMY, DUMMY);
            }
        }

        // all-miss sign accumulators: sign bit stays 1 iff every j missed
        unsigned mlo[NPAIR], mhi[NPAIR];
#pragma unroll
        for (int pr = 0; pr < NPAIR; pr++) { mlo[pr] = 0xFFFFFFFFu; mhi[pr] = 0xFFFFFFFFu; }

#pragma unroll 1
        for (int j = 0; j < JCHUNK; j += UNROLL) {
            unsigned tlo[NPAIR], thi[NPAIR];
#pragma unroll
            for (int u = 0; u < UNROLL; u++) {
                const ulonglong2* q = s_db + (j + u) * 5;
                const ulonglong2 q0 = q[0];
                const ulonglong2 q1 = q[1];
                const ulonglong2 q2 = q[2];
                const ulonglong2 q3 = q[3];
                const ulonglong2 q4 = q[4];
#pragma unroll
                for (int pr = 0; pr < NPAIR; pr++) {
                    // acc = dot - thr (both halves); hit iff acc >= +0
                    ull acc = fma2(pk[pr][0], q0.x, negt[pr]);
                    acc = fma2(pk[pr][1], q0.y, acc);
                    acc = fma2(pk[pr][2], q1.x, acc);
                    acc = fma2(pk[pr][3], q1.y, acc);
                    acc = fma2(pk[pr][4], q2.x, acc);
                    acc = fma2(pk[pr][5], q2.y, acc);
                    acc = fma2(pk[pr][6], q3.x, acc);
                    acc = fma2(pk[pr][7], q3.y, acc);
                    acc = fma2(pk[pr][8], q4.x, acc);
                    if (u == 0) {
                        tlo[pr] = (unsigned)acc;
                        thi[pr] = (unsigned)(acc >> 32);
                    } else {
                        // one 3-input LOP3 per word: m &= (t & acc)
                        mlo[pr] &= tlo[pr] & (unsigned)acc;
                        mhi[pr] &= thi[pr] & (unsigned)(acc >> 32);
                    }
                }
            }
        }

#pragma unroll
        for (int pr = 0; pr < NPAIR; pr++) {
            if (!(mlo[pr] & 0x80000000u) && pidx[pr].x < N_PATCH)
                ((volatile int*)g_hit)[pidx[pr].x] = 1;   // benign race: same value
            if (!(mhi[pr] & 0x80000000u) && pidx[pr].y < N_PATCH)
                ((volatile int*)g_hit)[pidx[pr].y] = 1;
        }
    }
}

// ------------------------- compaction --------------------------------------
__global__ void compact_kernel(int* __restrict__ outlist, int* __restrict__ cntslot) {
    int i = blockIdx.x * blockDim.x + threadIdx.x;
    bool surv = (i < N_PATCH) && (g_hit[i] == 0);
    unsigned ballot = __ballot_sync(0xFFFFFFFFu, surv);
    int lane = threadIdx.x & 31;
    int rank = __popc(ballot & ((1u << lane) - 1));
    int total = __popc(ballot);
    int basepos = 0;
    if (lane == 0 && total) basepos = atomicAdd(cntslot, total);
    basepos = __shfl_sync(0xFFFFFFFFu, basepos, 0);
    if (surv) outlist[basepos + rank] = i;
}

// ------------------------- gather (re-pair survivors) ----------------------
__global__ void gather_kernel(const int* __restrict__ list,
                              const int* __restrict__ cntp) {
    int cnt = *cntp;
    int np = (cnt + 1) >> 1;
    int p = blockIdx.x * blockDim.x + threadIdx.x;
    if (p >= np) return;
    int ia = list[2 * p];
    int ib = (2 * p + 1 < cnt) ? list[2 * p + 1] : DUMMY;
    float4 a0 = g_pp[ia * 3 + 0], a1 = g_pp[ia * 3 + 1], a2 = g_pp[ia * 3 + 2];
    float4 b0 = g_pp[ib * 3 + 0], b1 = g_pp[ib * 3 + 1], b2 = g_pp[ib * 3 + 2];
    ulonglong2* o = g_pk + (size_t)p * 5;
    o[0] = make_ulonglong2(pack2(a0.x, b0.x), pack2(a0.y, b0.y));
    o[1] = make_ulonglong2(pack2(a0.z, b0.z), pack2(a0.w, b0.w));
    o[2] = make_ulonglong2(pack2(a1.x, b1.x), pack2(a1.y, b1.y));
    o[3] = make_ulonglong2(pack2(a1.z, b1.z), pack2(a1.w, b1.w));
    o[4] = make_ulonglong2(pack2(a2.x, b2.x), pack2(a2.y, b2.y));
    g_idx[p] = make_int2(ia, ib);
}

// ------------------------- output kernel -----------------------------------
__global__ void out_kernel(const float4* __restrict__ patches4,
                           const float4* __restrict__ db4,
                           float4* __restrict__ out4) {
    int idx = blockIdx.x * blockDim.x + threadIdx.x;
    if (idx < HALF_OUT / 4) {
        out4[idx] = db4[idx];
    } else if (idx < TOTAL_OUT / 4) {
        int t4 = idx - HALF_OUT / 4;
        float4 v = patches4[t4];
        float w[4] = {v.x, v.y, v.z, v.w};
        int t = t4 * 4;
#pragma unroll
        for (int k = 0; k < 4; k++)
            if (g_hit[(t + k) / ROW]) w[k] = 0.0f;
        out4[idx] = make_float4(w[0], w[1], w[2], w[3]);
    }
}

// ------------------------- launch ------------------------------------------
extern "C" void kernel_launch(void* const* d_in, const int* in_sizes, int n_in,
                              void* d_out, int out_size) {
    const float* patches = (const float*)d_in[0];   // [16384][9]
    const float* db      = (const float*)d_in[1];   // [16384][9]

    int *list, *cnt;
    cudaGetSymbolAddress((void**)&list, g_list);
    cudaGetSymbolAddress((void**)&cnt,  g_cnt);

    prep_kernel<<<(N_DB + MAXPAIR + 255) / 256, 256>>>(patches, db);

    // Round 0: j [0, 2048), all 8192 pairs      -> 16 x 64 = 1024 blocks
    sim_kernel<<<dim3(16, 64), B_THREADS>>>(0, nullptr);
    compact_kernel<<<N_PATCH / 256, 256>>>(list, cnt + 0);
    gather_kernel<<<MAXPAIR / 256, 256>>>(list, cnt + 0);
    // Round 1: j [2048, 4096), survivors        -> 16 x 64 (grid-stride)
    sim_kernel<<<dim3(16, 64), B_THREADS>>>(2048, cnt + 0);
    compact_kernel<<<N_PATCH / 256, 256>>>(list, cnt + 1);
    gather_kernel<<<MAXPAIR / 256, 256>>>(list, cnt + 1);
    // Round 2: j [4096, 8192), survivors        -> 8 x 128
    sim_kernel<<<dim3(8, 128), B_THREADS>>>(4096, cnt + 1);
    compact_kernel<<<N_PATCH / 256, 256>>>(list, cnt + 2);
    gather_kernel<<<MAXPAIR / 256, 256>>>(list, cnt + 2);
    // Round 3: j [8192, 16384), survivors       -> 4 x 256
    sim_kernel<<<dim3(4, 256), B_THREADS>>>(8192, cnt + 2);

    out_kernel<<<(TOTAL_OUT / 4 + 255) / 256, 256>>>(
        (const float4*)patches, (const float4*)db, (float4*)d_out);
}